// round 13
// baseline (speedup 1.0000x reference)
#include <cuda_runtime.h>
#include <cstdint>
#include <cstddef>

#define B_   128
#define C_   2048
#define HW_  196
#define ND_  32
#define NA_  1845

#define THREADS 128         // 4 warps
#define CK      256         // floats per k-chunk (1KB per W row)
#define NCHUNK  8           // 2048 / 256
#define ATILE   16          // answer rows per block (4 warps x 4 rows)

// Scratch for attended features (cudaMalloc is forbidden) — 1 MB, L2-hot.
__device__ __align__(1024) float g_att[B_ * C_];

// ---- dynamic smem layout (bytes) ----
// W bufs 2x16KB at 0, X bufs 2x4KB at 32KB, control at 40KB. ~41KB total
// -> 5 blocks/SM (20 warps), W footprint 5*148*128KB ~= 95MB < L2.
#define X_OFF   32768
#define SM_LIST 40960                     // int[128]
#define SM_CNT  (SM_LIST + 512)
#define SM_IS64 (SM_CNT + 4)
#define SM_TOT  (SM_IS64 + 4)

// ---------------------------------------------------------------------------
// Kernel 1: attended[b][c] = (1/196) * sum_hw mask[b][hw] * features[b][c][hw]
// One warp per (b,c) row; ~78% of HBM peak — unchanged.
// ---------------------------------------------------------------------------
__global__ void __launch_bounds__(256) k_attend(const float* __restrict__ mask,
                                                const float* __restrict__ feat)
{
    int gw   = (blockIdx.x * 256 + threadIdx.x) >> 5;
    int lane = threadIdx.x & 31;
    if (gw >= B_ * C_) return;
    int b = gw >> 11;

    const float4* f  = (const float4*)(feat + (size_t)gw * HW_);
    const float4* mk = (const float4*)(mask + (size_t)b  * HW_);

    float4 a0 = f[lane], m0 = mk[lane];
    float s = a0.x * m0.x + a0.y * m0.y + a0.z * m0.z + a0.w * m0.w;
    if (lane < 17) {
        float4 a1 = f[lane + 32], m1 = mk[lane + 32];
        s += a1.x * m1.x + a1.y * m1.y + a1.z * m1.z + a1.w * m1.w;
    }
    #pragma unroll
    for (int o = 16; o; o >>= 1) s += __shfl_xor_sync(0xffffffffu, s, o);
    if (lane == 0) g_att[gw] = s * (1.0f / 196.0f);
}

// ---------------------------------------------------------------------------
// Helpers
// ---------------------------------------------------------------------------
__device__ __forceinline__ void fma2(unsigned long long& d,
                                     unsigned long long a,
                                     unsigned long long b)
{
    asm("fma.rn.f32x2 %0, %1, %2, %0;" : "+l"(d) : "l"(a), "l"(b));
}

__device__ __forceinline__ uint32_t smem_u32(const void* p) {
    uint32_t a;
    asm("{ .reg .u64 t; cvta.to.shared.u64 t, %1; cvt.u32.u64 %0, t; }"
        : "=r"(a) : "l"(p));
    return a;
}

__device__ __forceinline__ void cp16(uint32_t saddr, const void* gaddr) {
    asm volatile("cp.async.cg.shared.global [%0], [%1], 16;"
                 :: "r"(saddr), "l"(gaddr));
}
__device__ __forceinline__ void cp_commit() {
    asm volatile("cp.async.commit_group;");
}
template <int N>
__device__ __forceinline__ void cp_wait() {
    asm volatile("cp.async.wait_group %0;" :: "n"(N));
}

// ---------------------------------------------------------------------------
// Stage one k-chunk: W 16 rows x CK (16KB) + X 4 rows x CK (4KB).
// ---------------------------------------------------------------------------
__device__ __forceinline__ void issue_stage(uint32_t smb,
                                            const float* __restrict__ Wg,
                                            int k0, int buf, int tid,
                                            const int* bj)
{
    uint32_t wdst = smb + buf * 16384;
    #pragma unroll
    for (int i = 0; i < 8; i++) {                      // 1024 f4 / 128 thr
        int idx = i * 128 + tid;
        int row = idx >> 6, col = idx & 63;
        cp16(wdst + idx * 16, Wg + (size_t)row * C_ + k0 + col * 4);
    }
    uint32_t xdst = smb + X_OFF + buf * 4096;
    #pragma unroll
    for (int i = 0; i < 2; i++) {                      // 256 f4 / 128 thr
        int idx = i * 128 + tid;
        int j = idx >> 6, col = idx & 63;
        cp16(xdst + idx * 16, g_att + (size_t)bj[j] * C_ + k0 + col * 4);
    }
    cp_commit();
}

// ---------------------------------------------------------------------------
// One pass: 16 W rows x 4 samples, NBUF=2 cp.async pipeline. For groups
// beyond the first, the identical W stream re-hits L2 (128KB slice read
// ~6us earlier; chip footprint 95MB < L2) -> no extra DRAM.
// ---------------------------------------------------------------------------
__device__ __forceinline__ void run_pass(uint32_t smb, char* sm,
                                         const float* __restrict__ Wg,
                                         int tid, int lane, int warp,
                                         const int* bj,
                                         int a0c, int a0nom, int d,
                                         const float* __restrict__ bias,
                                         float* __restrict__ out)
{
    unsigned long long acc[4][4];
    #pragma unroll
    for (int r = 0; r < 4; r++)
        #pragma unroll
        for (int j = 0; j < 4; j++) acc[r][j] = 0ull;

    issue_stage(smb, Wg, 0, 0, tid, bj);

    for (int k = 0; k < NCHUNK; k++) {
        int buf = k & 1;
        if (k + 1 < NCHUNK) {
            // buf (k+1)&1 last read at stage k-1; trailing barrier passed.
            issue_stage(smb, Wg, (k + 1) * CK, (k + 1) & 1, tid, bj);
            cp_wait<1>();
        } else {
            cp_wait<0>();
        }
        __syncthreads();                               // stage k visible

        const float* Wb = (const float*)(sm + buf * 16384);
        const float* Xb = (const float*)(sm + X_OFF + buf * 4096);
        #pragma unroll
        for (int st = 0; st < 2; st++) {               // CK/4 = 64 float4
            int c = lane + st * 32;
            ulonglong2 w[4];
            #pragma unroll
            for (int r = 0; r < 4; r++)
                w[r] = ((const ulonglong2*)(Wb + (warp * 4 + r) * CK))[c];
            #pragma unroll
            for (int j = 0; j < 4; j++) {
                ulonglong2 x = ((const ulonglong2*)(Xb + j * CK))[c];
                #pragma unroll
                for (int r = 0; r < 4; r++) {
                    fma2(acc[r][j], w[r].x, x.x);
                    fma2(acc[r][j], w[r].y, x.y);
                }
            }
        }
        __syncthreads();                               // WAR on buf
    }

    #pragma unroll
    for (int r = 0; r < 4; r++) {
        int a = a0c + warp * 4 + r;
        #pragma unroll
        for (int j = 0; j < 4; j++) {                  // padded j idempotent
            float v = __uint_as_float((unsigned)(acc[r][j] & 0xffffffffu))
                    + __uint_as_float((unsigned)(acc[r][j] >> 32));
            #pragma unroll
            for (int o = 16; o; o >>= 1) v += __shfl_xor_sync(0xffffffffu, v, o);
            if (lane == 0 && a >= a0nom)
                out[(size_t)bj[j] * NA_ + a] = v + bias[(size_t)d * NA_ + a];
        }
    }
}

// ---------------------------------------------------------------------------
// Kernel 2: grouped GEMM. Grid (116, 32); single uniform pass shape.
// ---------------------------------------------------------------------------
__global__ void __launch_bounds__(THREADS, 5) k_gemm(const void* __restrict__ inst_raw,
                                                     const float* __restrict__ W,
                                                     const float* __restrict__ bias,
                                                     float* __restrict__ out)
{
    extern __shared__ char sm[];
    uint32_t smb = smem_u32(sm);
    int* s_list = (int*)(sm + SM_LIST);
    int* s_cnt  = (int*)(sm + SM_CNT);
    int* s_is64 = (int*)(sm + SM_IS64);

    if (threadIdx.x == 0) {
        // Detect int64 vs int32 instance layout (values 0..31 => odd words 0).
        const unsigned* pw = (const unsigned*)inst_raw;
        unsigned orv = 0;
        for (int i = 1; i < 128; i += 2) orv |= pw[i];
        *s_is64 = (orv == 0) ? 1 : 0;
        *s_cnt  = 0;
    }
    __syncthreads();

    int d = blockIdx.y;
    {   // 128 threads scan all 128 instances
        int v = *s_is64 ? (int)((const long long*)inst_raw)[threadIdx.x]
                        : ((const int*)inst_raw)[threadIdx.x];
        if (v == d) {
            int p = atomicAdd(s_cnt, 1);
            s_list[p] = threadIdx.x;
        }
    }
    __syncthreads();

    int m = *s_cnt;
    if (m == 0) return;                                // unused descriptor

    int tid  = threadIdx.x;
    int lane = tid & 31;
    int warp = tid >> 5;
    int a0nom = blockIdx.x * ATILE;
    int a0c   = a0nom > NA_ - ATILE ? NA_ - ATILE : a0nom;
    const float* W0 = W + ((size_t)d * NA_ + a0c) * C_;

    // s_list is written once above and never modified -> bj reads are safe
    // at any point (no cross-pass snapshot hazards).
    for (int mbase = 0; mbase < m; mbase += 4) {
        int mc = m - mbase; if (mc > 4) mc = 4;
        int bj[4];
        #pragma unroll
        for (int j = 0; j < 4; j++)
            bj[j] = s_list[mbase + (j < mc ? j : mc - 1)];

        run_pass(smb, sm, W0, tid, lane, warp, bj, a0c, a0nom, d, bias, out);
    }
}

// ---------------------------------------------------------------------------
// Inputs (metadata order): mask f32[128,1,14,14], features f32[128,2048,14,14],
// instance int[128], W f32[32,1845,2048], b f32[32,1845]. Output f32[128,1845].
// ---------------------------------------------------------------------------
extern "C" void kernel_launch(void* const* d_in, const int* in_sizes, int n_in,
                              void* d_out, int out_size)
{
    const float* mask = (const float*)d_in[0];
    const float* feat = (const float*)d_in[1];
    const void*  inst = d_in[2];
    const float* W    = (const float*)d_in[3];
    const float* bias = (const float*)d_in[4];
    float* out = (float*)d_out;

    int blocks1 = (B_ * C_) / 8;                       // warp per (b,c) row
    k_attend<<<blocks1, 256>>>(mask, feat);

    cudaFuncSetAttribute(k_gemm, cudaFuncAttributeMaxDynamicSharedMemorySize,
                         SM_TOT);
    dim3 g2((NA_ + ATILE - 1) / ATILE, ND_);           // (116, 32)
    k_gemm<<<g2, THREADS, SM_TOT>>>(inst, W, bias, out);
}

// round 14
// speedup vs baseline: 1.1310x; 1.1310x over previous
#include <cuda_runtime.h>
#include <cstdint>
#include <cstddef>

#define B_   128
#define C_   2048
#define HW_  196
#define ND_  32
#define NA_  1845

#define THREADS 128         // 4 warps
#define CK      256         // floats per k-chunk (1KB per W row)
#define NCHUNK  8           // 2048 / 256
#define ATILE   16          // answer rows per block (4 warps x 4 rows)

// Scratch for attended features (cudaMalloc is forbidden) — 1 MB, L2-hot.
__device__ __align__(1024) float g_att[B_ * C_];

// ---- dynamic smem layout (bytes) ----
// W bufs 2x16KB at 0, X bufs 2x4KB at 32KB, control at 40KB.
// PADDED to 52KB: forces exactly 4 blocks/SM (5x52 > 228KB), which caps the
// chip-wide live W footprint at 4*148*128KB = 75MB -- the regime where R4
// demonstrated same-slice rereads re-hit L2 instead of DRAM.
#define X_OFF   32768
#define SM_LIST 40960                     // int[128]
#define SM_CNT  (SM_LIST + 512)
#define SM_IS64 (SM_CNT + 4)
#define SM_TOT  53248                     // 52KB -> exactly 4 blocks/SM

// ---------------------------------------------------------------------------
// Kernel 1: attended[b][c] = (1/196) * sum_hw mask[b][hw] * features[b][c][hw]
// One warp per (b,c) row; measured ~6.4TB/s = at the ~6.3TB/s LTS cap.
// ---------------------------------------------------------------------------
__global__ void __launch_bounds__(256) k_attend(const float* __restrict__ mask,
                                                const float* __restrict__ feat)
{
    int gw   = (blockIdx.x * 256 + threadIdx.x) >> 5;
    int lane = threadIdx.x & 31;
    if (gw >= B_ * C_) return;
    int b = gw >> 11;

    const float4* f  = (const float4*)(feat + (size_t)gw * HW_);
    const float4* mk = (const float4*)(mask + (size_t)b  * HW_);

    float4 a0 = f[lane], m0 = mk[lane];
    float s = a0.x * m0.x + a0.y * m0.y + a0.z * m0.z + a0.w * m0.w;
    if (lane < 17) {
        float4 a1 = f[lane + 32], m1 = mk[lane + 32];
        s += a1.x * m1.x + a1.y * m1.y + a1.z * m1.z + a1.w * m1.w;
    }
    #pragma unroll
    for (int o = 16; o; o >>= 1) s += __shfl_xor_sync(0xffffffffu, s, o);
    if (lane == 0) g_att[gw] = s * (1.0f / 196.0f);
}

// ---------------------------------------------------------------------------
// Helpers
// ---------------------------------------------------------------------------
__device__ __forceinline__ void fma2(unsigned long long& d,
                                     unsigned long long a,
                                     unsigned long long b)
{
    asm("fma.rn.f32x2 %0, %1, %2, %0;" : "+l"(d) : "l"(a), "l"(b));
}

__device__ __forceinline__ uint32_t smem_u32(const void* p) {
    uint32_t a;
    asm("{ .reg .u64 t; cvta.to.shared.u64 t, %1; cvt.u32.u64 %0, t; }"
        : "=r"(a) : "l"(p));
    return a;
}

__device__ __forceinline__ void cp16(uint32_t saddr, const void* gaddr) {
    asm volatile("cp.async.cg.shared.global [%0], [%1], 16;"
                 :: "r"(saddr), "l"(gaddr));
}
__device__ __forceinline__ void cp_commit() {
    asm volatile("cp.async.commit_group;");
}
template <int N>
__device__ __forceinline__ void cp_wait() {
    asm volatile("cp.async.wait_group %0;" :: "n"(N));
}

// ---------------------------------------------------------------------------
// Stage one k-chunk: W 16 rows x CK (16KB) + X 4 rows x CK (4KB).
// ---------------------------------------------------------------------------
__device__ __forceinline__ void issue_stage(uint32_t smb,
                                            const float* __restrict__ Wg,
                                            int k0, int buf, int tid,
                                            const int* bj)
{
    uint32_t wdst = smb + buf * 16384;
    #pragma unroll
    for (int i = 0; i < 8; i++) {                      // 1024 f4 / 128 thr
        int idx = i * 128 + tid;
        int row = idx >> 6, col = idx & 63;
        cp16(wdst + idx * 16, Wg + (size_t)row * C_ + k0 + col * 4);
    }
    uint32_t xdst = smb + X_OFF + buf * 4096;
    #pragma unroll
    for (int i = 0; i < 2; i++) {                      // 256 f4 / 128 thr
        int idx = i * 128 + tid;
        int j = idx >> 6, col = idx & 63;
        cp16(xdst + idx * 16, g_att + (size_t)bj[j] * C_ + k0 + col * 4);
    }
    cp_commit();
}

// ---------------------------------------------------------------------------
// One pass: 16 W rows x 4 samples, NBUF=2 cp.async pipeline. Groups beyond
// the first re-stream the block's 128KB W slice; at 75MB chip footprint
// those rereads come from L2 (R4-verified regime), not DRAM.
// ---------------------------------------------------------------------------
__device__ __forceinline__ void run_pass(uint32_t smb, char* sm,
                                         const float* __restrict__ Wg,
                                         int tid, int lane, int warp,
                                         const int* bj,
                                         int a0c, int a0nom, int d,
                                         const float* __restrict__ bias,
                                         float* __restrict__ out)
{
    unsigned long long acc[4][4];
    #pragma unroll
    for (int r = 0; r < 4; r++)
        #pragma unroll
        for (int j = 0; j < 4; j++) acc[r][j] = 0ull;

    issue_stage(smb, Wg, 0, 0, tid, bj);

    for (int k = 0; k < NCHUNK; k++) {
        int buf = k & 1;
        if (k + 1 < NCHUNK) {
            // buf (k+1)&1 last read at stage k-1; trailing barrier passed.
            issue_stage(smb, Wg, (k + 1) * CK, (k + 1) & 1, tid, bj);
            cp_wait<1>();
        } else {
            cp_wait<0>();
        }
        __syncthreads();                               // stage k visible

        const float* Wb = (const float*)(sm + buf * 16384);
        const float* Xb = (const float*)(sm + X_OFF + buf * 4096);
        #pragma unroll
        for (int st = 0; st < 2; st++) {               // CK/4 = 64 float4
            int c = lane + st * 32;
            ulonglong2 w[4];
            #pragma unroll
            for (int r = 0; r < 4; r++)
                w[r] = ((const ulonglong2*)(Wb + (warp * 4 + r) * CK))[c];
            #pragma unroll
            for (int j = 0; j < 4; j++) {
                ulonglong2 x = ((const ulonglong2*)(Xb + j * CK))[c];
                #pragma unroll
                for (int r = 0; r < 4; r++) {
                    fma2(acc[r][j], w[r].x, x.x);
                    fma2(acc[r][j], w[r].y, x.y);
                }
            }
        }
        __syncthreads();                               // WAR on buf
    }

    #pragma unroll
    for (int r = 0; r < 4; r++) {
        int a = a0c + warp * 4 + r;
        #pragma unroll
        for (int j = 0; j < 4; j++) {                  // padded j idempotent
            float v = __uint_as_float((unsigned)(acc[r][j] & 0xffffffffu))
                    + __uint_as_float((unsigned)(acc[r][j] >> 32));
            #pragma unroll
            for (int o = 16; o; o >>= 1) v += __shfl_xor_sync(0xffffffffu, v, o);
            if (lane == 0 && a >= a0nom)
                out[(size_t)bj[j] * NA_ + a] = v + bias[(size_t)d * NA_ + a];
        }
    }
}

// ---------------------------------------------------------------------------
// Kernel 2: grouped GEMM. Grid (116, 32); single uniform pass shape.
// ---------------------------------------------------------------------------
__global__ void __launch_bounds__(THREADS, 4) k_gemm(const void* __restrict__ inst_raw,
                                                     const float* __restrict__ W,
                                                     const float* __restrict__ bias,
                                                     float* __restrict__ out)
{
    extern __shared__ char sm[];
    uint32_t smb = smem_u32(sm);
    int* s_list = (int*)(sm + SM_LIST);
    int* s_cnt  = (int*)(sm + SM_CNT);
    int* s_is64 = (int*)(sm + SM_IS64);

    if (threadIdx.x == 0) {
        // Detect int64 vs int32 instance layout (values 0..31 => odd words 0).
        const unsigned* pw = (const unsigned*)inst_raw;
        unsigned orv = 0;
        for (int i = 1; i < 128; i += 2) orv |= pw[i];
        *s_is64 = (orv == 0) ? 1 : 0;
        *s_cnt  = 0;
    }
    __syncthreads();

    int d = blockIdx.y;
    {   // 128 threads scan all 128 instances
        int v = *s_is64 ? (int)((const long long*)inst_raw)[threadIdx.x]
                        : ((const int*)inst_raw)[threadIdx.x];
        if (v == d) {
            int p = atomicAdd(s_cnt, 1);
            s_list[p] = threadIdx.x;
        }
    }
    __syncthreads();

    int m = *s_cnt;
    if (m == 0) return;                                // unused descriptor

    int tid  = threadIdx.x;
    int lane = tid & 31;
    int warp = tid >> 5;
    int a0nom = blockIdx.x * ATILE;
    int a0c   = a0nom > NA_ - ATILE ? NA_ - ATILE : a0nom;
    const float* W0 = W + ((size_t)d * NA_ + a0c) * C_;

    // s_list is written once above and never modified -> bj reads are safe
    // at any point (no cross-pass snapshot hazards).
    for (int mbase = 0; mbase < m; mbase += 4) {
        int mc = m - mbase; if (mc > 4) mc = 4;
        int bj[4];
        #pragma unroll
        for (int j = 0; j < 4; j++)
            bj[j] = s_list[mbase + (j < mc ? j : mc - 1)];

        run_pass(smb, sm, W0, tid, lane, warp, bj, a0c, a0nom, d, bias, out);
    }
}

// ---------------------------------------------------------------------------
// Inputs (metadata order): mask f32[128,1,14,14], features f32[128,2048,14,14],
// instance int[128], W f32[32,1845,2048], b f32[32,1845]. Output f32[128,1845].
// ---------------------------------------------------------------------------
extern "C" void kernel_launch(void* const* d_in, const int* in_sizes, int n_in,
                              void* d_out, int out_size)
{
    const float* mask = (const float*)d_in[0];
    const float* feat = (const float*)d_in[1];
    const void*  inst = d_in[2];
    const float* W    = (const float*)d_in[3];
    const float* bias = (const float*)d_in[4];
    float* out = (float*)d_out;

    int blocks1 = (B_ * C_) / 8;                       // warp per (b,c) row
    k_attend<<<blocks1, 256>>>(mask, feat);

    cudaFuncSetAttribute(k_gemm, cudaFuncAttributeMaxDynamicSharedMemorySize,
                         SM_TOT);
    dim3 g2((NA_ + ATILE - 1) / ATILE, ND_);           // (116, 32)
    k_gemm<<<g2, THREADS, SM_TOT>>>(inst, W, bias, out);
}